// round 4
// baseline (speedup 1.0000x reference)
#include <cuda_runtime.h>
#include <math.h>

#define N_NODES 50000
#define N_EDGES 800000
#define D 128
#define HEADS 8
#define UNITS 16
#define PAD 96                 // max supported in-degree (Poisson(16): P(>=96) ~ 1e-40)

#define GEMM_BLOCKS 3125       // 50000 / 16 nodes per block
#define FILL_BLOCKS 784

// ---------------- device scratch ----------------
__device__ float g_xp[N_NODES * D];          // 25.6 MB
__device__ int   g_cnt[N_NODES];             // in-degree counters (self-cleaning)
__device__ int   g_esrc[N_NODES * PAD];      // 19.2 MB padded CSR slots

__device__ __forceinline__ float lrelu(float v) {
    return fmaxf(v, 0.2f * v);               // branchless: valid since 0.2 < 1
}

// ---------------- kernel 1: gemm (blocks [0,GEMM_BLOCKS)) || fill (rest) ----------------
__global__ void build_kernel(const float* __restrict__ x, const float* __restrict__ W,
                             const int* __restrict__ edges) {
    if (blockIdx.x < GEMM_BLOCKS) {
        // ---- xp = x @ W : 16 nodes per 128-thread block, thread t owns column t ----
        __shared__ float xs[16][D];
        int node0 = blockIdx.x * 16;
        int t = threadIdx.x;

        #pragma unroll
        for (int m = 0; m < 16; m++)
            xs[m][t] = x[(node0 + m) * D + t];          // grid exactly covers 50000
        __syncthreads();

        float acc[16];
        #pragma unroll
        for (int m = 0; m < 16; m++) acc[m] = 0.0f;

        #pragma unroll 4
        for (int d = 0; d < D; d++) {
            float w = W[d * D + t];
            #pragma unroll
            for (int m = 0; m < 16; m++) acc[m] += xs[m][d] * w;
        }

        #pragma unroll
        for (int m = 0; m < 16; m++)
            g_xp[(node0 + m) * D + t] = acc[m];
    } else {
        // ---- fill: scatter sources into per-target padded slots ----
        int tid = (blockIdx.x - GEMM_BLOCKS) * 128 + threadIdx.x;
        int nthreads = FILL_BLOCKS * 128;
        const int4* e4 = (const int4*)edges;            // 2 edges per int4
        for (int i = tid; i < N_EDGES / 2; i += nthreads) {
            int4 e = e4[i];
            int p0 = atomicAdd(&g_cnt[e.y], 1);
            if (p0 < PAD) g_esrc[e.y * PAD + p0] = e.x;
            int p1 = atomicAdd(&g_cnt[e.w], 1);
            if (p1 < PAD) g_esrc[e.w * PAD + p1] = e.z;
        }
    }
}

// ---------------- kernel 2: fused GAT pass, warp per target ----------------
__global__ void gat_kernel(const float* __restrict__ ka,
                           const float* __restrict__ ba,
                           const float* __restrict__ bias,
                           float* __restrict__ out) {
    int t = blockIdx.x * (blockDim.x >> 5) + (threadIdx.x >> 5);
    if (t >= N_NODES) return;
    int lane = threadIdx.x & 31;

    int deg = g_cnt[t];
    if (lane == 0) g_cnt[t] = 0;                 // self-clean for next replay
    deg = min(deg, PAD);
    const int* __restrict__ srcs = g_esrc + t * PAD;

    float4 k4  = ((const float4*)ka)[lane];
    float4 ba4 = ((const float4*)ba)[lane];
    float4 tb  = ((const float4*)(g_xp + (size_t)t * D))[lane];
    tb.x += 2.0f * ba4.x; tb.y += 2.0f * ba4.y;
    tb.z += 2.0f * ba4.z; tb.w += 2.0f * ba4.w;

    float4 acc = make_float4(0.0f, 0.0f, 0.0f, 0.0f);
    float wsum = 0.0f;

    // two-ahead software pipeline, unrolled x2
    float4 a0, a1;
    if (deg > 0) a0 = ((const float4*)(g_xp + (size_t)srcs[0] * D))[lane];
    if (deg > 1) a1 = ((const float4*)(g_xp + (size_t)srcs[1] * D))[lane];

    int i = 0;
    for (; i + 2 <= deg; i += 2) {
        float4 c0 = a0, c1 = a1;
        if (i + 2 < deg) a0 = ((const float4*)(g_xp + (size_t)srcs[i + 2] * D))[lane];
        if (i + 3 < deg) a1 = ((const float4*)(g_xp + (size_t)srcs[i + 3] * D))[lane];

        float p0 = lrelu(c0.x + tb.x) * k4.x + lrelu(c0.y + tb.y) * k4.y
                 + lrelu(c0.z + tb.z) * k4.z + lrelu(c0.w + tb.w) * k4.w;
        float p1 = lrelu(c1.x + tb.x) * k4.x + lrelu(c1.y + tb.y) * k4.y
                 + lrelu(c1.z + tb.z) * k4.z + lrelu(c1.w + tb.w) * k4.w;

        p0 += __shfl_xor_sync(0xffffffffu, p0, 1);
        p1 += __shfl_xor_sync(0xffffffffu, p1, 1);
        p0 += __shfl_xor_sync(0xffffffffu, p0, 2);
        p1 += __shfl_xor_sync(0xffffffffu, p1, 2);

        float w0 = __expf(p0);
        float w1 = __expf(p1);
        wsum += w0 + w1;
        acc.x += w0 * c0.x + w1 * c1.x;
        acc.y += w0 * c0.y + w1 * c1.y;
        acc.z += w0 * c0.z + w1 * c1.z;
        acc.w += w0 * c0.w + w1 * c1.w;
    }
    if (i < deg) {
        float4 c0 = a0;
        float p = lrelu(c0.x + tb.x) * k4.x + lrelu(c0.y + tb.y) * k4.y
                + lrelu(c0.z + tb.z) * k4.z + lrelu(c0.w + tb.w) * k4.w;
        p += __shfl_xor_sync(0xffffffffu, p, 1);
        p += __shfl_xor_sync(0xffffffffu, p, 2);
        float w = __expf(p);
        wsum += w;
        acc.x += w * c0.x; acc.y += w * c0.y;
        acc.z += w * c0.z; acc.w += w * c0.w;
    }

    float inv = 1.0f / (wsum + 1e-7f);
    float4 b4 = ((const float4*)bias)[lane];
    float v[4] = { acc.x * inv + b4.x, acc.y * inv + b4.y,
                   acc.z * inv + b4.z, acc.w * inv + b4.w };
    #pragma unroll
    for (int j = 0; j < 4; j++) {
        float u = v[j];
        float c = 0.7978845608028654f * (u + 0.044715f * u * u * u);
        v[j] = 0.5f * u * (1.0f + tanhf(c));
    }
    ((float4*)(out + (size_t)t * D))[lane] = make_float4(v[0], v[1], v[2], v[3]);
}

// ---------------- launch ----------------
extern "C" void kernel_launch(void* const* d_in, const int* in_sizes, int n_in,
                              void* d_out, int out_size) {
    const float* x     = (const float*)d_in[0];
    const int*   edges = (const int*)  d_in[1];
    const float* W     = (const float*)d_in[2];
    const float* ka    = (const float*)d_in[3];
    const float* ba    = (const float*)d_in[4];
    const float* bias  = (const float*)d_in[5];
    float* out = (float*)d_out;

    (void)in_sizes; (void)n_in; (void)out_size;

    build_kernel<<<GEMM_BLOCKS + FILL_BLOCKS, 128>>>(x, W, edges);
    gat_kernel<<<(N_NODES + 7) / 8, 256>>>(ka, ba, bias, out);
}

// round 5
// speedup vs baseline: 1.0245x; 1.0245x over previous
#include <cuda_runtime.h>
#include <math.h>

#define N_NODES 50000
#define N_EDGES 800000
#define D 128
#define HEADS 8
#define UNITS 16
#define PAD 96                 // max supported in-degree (Poisson(16): P(>=96) ~ 1e-40)

// ---------------- device scratch ----------------
__device__ float g_xp[N_NODES * D];          // 25.6 MB
__device__ int   g_cnt[N_NODES];             // in-degree counters (zero-init; self-cleaning)
__device__ int   g_esrc[N_NODES * PAD];      // 19.2 MB padded CSR slots

__device__ __forceinline__ float lrelu(float v) {
    return fmaxf(v, 0.2f * v);               // branchless: valid since 0.2 < 1
}

// ---------------- kernel 1: xp = x @ W ----------------
// 128 threads/block, 16 nodes/block; thread t owns output column t. (R3-proven)
__global__ void gemm_kernel(const float* __restrict__ x, const float* __restrict__ W) {
    __shared__ float xs[16][D];
    int node0 = blockIdx.x * 16;
    int t = threadIdx.x;

    #pragma unroll
    for (int m = 0; m < 16; m++)
        xs[m][t] = x[(node0 + m) * D + t];          // grid exactly covers 50000
    __syncthreads();

    float acc[16];
    #pragma unroll
    for (int m = 0; m < 16; m++) acc[m] = 0.0f;

    #pragma unroll 4
    for (int d = 0; d < D; d++) {
        float w = W[d * D + t];
        #pragma unroll
        for (int m = 0; m < 16; m++) acc[m] += xs[m][d] * w;
    }

    #pragma unroll
    for (int m = 0; m < 16; m++)
        g_xp[(node0 + m) * D + t] = acc[m];
}

// ---------------- kernel 2: scatter sources into per-target padded slots ----------------
__global__ void fill_kernel(const int* __restrict__ edges) {
    int i = blockIdx.x * blockDim.x + threadIdx.x;
    if (i >= N_EDGES / 2) return;
    int4 e = ((const int4*)edges)[i];               // 2 edges per int4
    int p0 = atomicAdd(&g_cnt[e.y], 1);
    if (p0 < PAD) g_esrc[e.y * PAD + p0] = e.x;
    int p1 = atomicAdd(&g_cnt[e.w], 1);
    if (p1 < PAD) g_esrc[e.w * PAD + p1] = e.z;
}

// ---------------- kernel 3: fused GAT pass, warp per target ----------------
__global__ void gat_kernel(const float* __restrict__ ka,
                           const float* __restrict__ ba,
                           const float* __restrict__ bias,
                           float* __restrict__ out) {
    int t = blockIdx.x * (blockDim.x >> 5) + (threadIdx.x >> 5);
    if (t >= N_NODES) return;
    int lane = threadIdx.x & 31;

    int deg = g_cnt[t];
    if (lane == 0) g_cnt[t] = 0;                    // self-clean for next replay
    deg = min(deg, PAD);
    const int* __restrict__ srcs = g_esrc + t * PAD;

    // warp-cooperative preload of source indices: no list loads inside the loop
    int sidx[PAD / 32];
    #pragma unroll
    for (int j = 0; j < PAD / 32; j++) {
        int idx = j * 32 + lane;
        sidx[j] = (idx < deg) ? srcs[idx] : 0;
    }
    #define SRC_AT(i) __shfl_sync(0xffffffffu, sidx[(i) >> 5], (i) & 31)

    float4 k4  = ((const float4*)ka)[lane];
    float4 ba4 = ((const float4*)ba)[lane];
    float4 tb  = ((const float4*)(g_xp + (size_t)t * D))[lane];
    tb.x += 2.0f * ba4.x; tb.y += 2.0f * ba4.y;
    tb.z += 2.0f * ba4.z; tb.w += 2.0f * ba4.w;

    float4 acc = make_float4(0.0f, 0.0f, 0.0f, 0.0f);
    float wsum = 0.0f;

    // R3-proven 1-ahead software pipeline
    float4 a, a_nxt;
    if (deg > 0) a_nxt = ((const float4*)(g_xp + (size_t)SRC_AT(0) * D))[lane];

    for (int i = 0; i < deg; i++) {
        a = a_nxt;
        if (i + 1 < deg)
            a_nxt = ((const float4*)(g_xp + (size_t)SRC_AT(i + 1) * D))[lane];

        float p = lrelu(a.x + tb.x) * k4.x
                + lrelu(a.y + tb.y) * k4.y
                + lrelu(a.z + tb.z) * k4.z
                + lrelu(a.w + tb.w) * k4.w;
        p += __shfl_xor_sync(0xffffffffu, p, 1);
        p += __shfl_xor_sync(0xffffffffu, p, 2);

        float w = __expf(p);
        wsum  += w;
        acc.x += w * a.x; acc.y += w * a.y;
        acc.z += w * a.z; acc.w += w * a.w;
    }
    #undef SRC_AT

    float inv = 1.0f / (wsum + 1e-7f);
    float4 b4 = ((const float4*)bias)[lane];
    float v[4] = { acc.x * inv + b4.x, acc.y * inv + b4.y,
                   acc.z * inv + b4.z, acc.w * inv + b4.w };
    #pragma unroll
    for (int j = 0; j < 4; j++) {
        float u = v[j];
        float c = 0.7978845608028654f * (u + 0.044715f * u * u * u);
        v[j] = 0.5f * u * (1.0f + tanhf(c));
    }
    ((float4*)(out + (size_t)t * D))[lane] = make_float4(v[0], v[1], v[2], v[3]);
}

// ---------------- launch ----------------
extern "C" void kernel_launch(void* const* d_in, const int* in_sizes, int n_in,
                              void* d_out, int out_size) {
    const float* x     = (const float*)d_in[0];
    const int*   edges = (const int*)  d_in[1];
    const float* W     = (const float*)d_in[2];
    const float* ka    = (const float*)d_in[3];
    const float* ba    = (const float*)d_in[4];
    const float* bias  = (const float*)d_in[5];
    float* out = (float*)d_out;

    (void)in_sizes; (void)n_in; (void)out_size;

    gemm_kernel<<<N_NODES / 16, 128>>>(x, W);
    fill_kernel<<<(N_EDGES / 2 + 255) / 256, 256>>>(edges);
    gat_kernel<<<(N_NODES + 7) / 8, 256>>>(ka, ba, bias, out);
}